// round 14
// baseline (speedup 1.0000x reference)
#include <cuda_runtime.h>
#include <math.h>

#define NN 100000
#define NE 1600000
#define HH 128
#define NC 40
#define NB 98          // ceil(NN/1024)
#define NDB 1024       // degree buckets

// ---------------- scratch ----------------
__device__ float g_h[NN * HH];
__device__ float g_hnew[NN * HH];
__device__ float g_sel[NN * HH];
__device__ float g_cp[NN];
__device__ int   g_counts[NN];
__device__ int   g_offsets[NN];
__device__ int   g_cursor[NN];
__device__ int   g_csr[NE];
__device__ int   g_bsums[128];
__device__ int   g_boffs[128];
__device__ int   g_dhist[NDB];
__device__ int   g_dcur[NDB];
__device__ int   g_perm[NN];    // degree-sorted node order
__device__ float g_Wpad[HH * HH];
__device__ float g_bpad[HH];

// ---------------- small utility kernels ----------------
__global__ void zero_counts_k() {
    int i = blockIdx.x * blockDim.x + threadIdx.x;
    if (i < NN) g_counts[i] = 0;
    if (i < NDB) g_dhist[i] = 0;
}

__global__ void pad_post_k(const float* __restrict__ Wp, const float* __restrict__ bp) {
    int i = blockIdx.x * blockDim.x + threadIdx.x;
    if (i < HH * HH) {
        int k = i / HH, c = i % HH;
        g_Wpad[i] = (c < NC) ? Wp[k * NC + c] : 0.0f;
    }
    if (i < HH) g_bpad[i] = (i < NC) ? bp[i] : 0.0f;
}

__global__ void hist_k(const int* __restrict__ dst) {
    int e = blockIdx.x * blockDim.x + threadIdx.x;
    if (e < NE) atomicAdd(&g_counts[dst[e]], 1);
}

__global__ void scan1_k() {
    __shared__ int sh[1024];
    int t = threadIdx.x;
    int i = blockIdx.x * 1024 + t;
    int v = (i < NN) ? g_counts[i] : 0;
    sh[t] = v;
    __syncthreads();
#pragma unroll
    for (int off = 1; off < 1024; off <<= 1) {
        int x = 0;
        if (t >= off) x = sh[t - off];
        __syncthreads();
        if (t >= off) sh[t] += x;
        __syncthreads();
    }
    int incl = sh[t];
    if (i < NN) g_offsets[i] = incl - v;
    if (t == 1023) g_bsums[blockIdx.x] = incl;
}

__global__ void scan2_k() {
    __shared__ int sh[128];
    int t = threadIdx.x;
    int v = (t < NB) ? g_bsums[t] : 0;
    sh[t] = v;
    __syncthreads();
#pragma unroll
    for (int off = 1; off < 128; off <<= 1) {
        int x = 0;
        if (t >= off) x = sh[t - off];
        __syncthreads();
        if (t >= off) sh[t] += x;
        __syncthreads();
    }
    g_boffs[t] = sh[t] - v;
}

__global__ void scan3_k() {
    int i = blockIdx.x * 1024 + threadIdx.x;
    if (i < NN) {
        int off = g_offsets[i] + g_boffs[blockIdx.x];
        g_offsets[i] = off;
        g_cursor[i]  = off;
        g_cp[i]      = 1.0f;
        // degree histogram for the sort
        int d = g_counts[i];
        atomicAdd(&g_dhist[d < NDB ? d : NDB - 1], 1);
    }
}

__global__ void fill_k(const int* __restrict__ src, const int* __restrict__ dst) {
    int e = blockIdx.x * blockDim.x + threadIdx.x;
    if (e < NE) {
        int d = dst[e];
        int p = atomicAdd(&g_cursor[d], 1);
        g_csr[p] = src[e];
    }
}

// exclusive scan over the 1024 degree buckets (single block)
__global__ void dscan_k() {
    __shared__ int sh[NDB];
    int t = threadIdx.x;
    int v = g_dhist[t];
    sh[t] = v;
    __syncthreads();
#pragma unroll
    for (int off = 1; off < NDB; off <<= 1) {
        int x = 0;
        if (t >= off) x = sh[t - off];
        __syncthreads();
        if (t >= off) sh[t] += x;
        __syncthreads();
    }
    g_dcur[t] = sh[t] - v;   // exclusive offset = running cursor
}

// scatter nodes into degree-sorted order
__global__ void dscatter_k() {
    int i = blockIdx.x * blockDim.x + threadIdx.x;
    if (i < NN) {
        int d = g_counts[i];
        int b = d < NDB ? d : NDB - 1;
        int pos = atomicAdd(&g_dcur[b], 1);
        g_perm[pos] = i;
    }
}

// ---------------- bf16 split helpers (pure bit math) ----------------
__device__ __forceinline__ unsigned bf16rn(float f) {
    unsigned b = __float_as_uint(f);
    return (b + 0x7fffu + ((b >> 16) & 1u)) >> 16;   // RNE
}

__device__ __forceinline__ void split2(float x, float y, unsigned& hi, unsigned& lo) {
    unsigned hx = bf16rn(x), hy = bf16rn(y);
    float rx = x - __uint_as_float(hx << 16);
    float ry = y - __uint_as_float(hy << 16);
    hi = hx | (hy << 16);
    lo = bf16rn(rx) | (bf16rn(ry) << 16);
}

// ---------------- MMA helpers ----------------
__device__ __forceinline__ void ldm_x4(unsigned* r, unsigned addr) {
    asm volatile("ldmatrix.sync.aligned.m8n8.x4.shared.b16 {%0,%1,%2,%3}, [%4];"
                 : "=r"(r[0]), "=r"(r[1]), "=r"(r[2]), "=r"(r[3]) : "r"(addr));
}

__device__ __forceinline__ void ldm_x4t(unsigned* r, unsigned addr) {
    asm volatile("ldmatrix.sync.aligned.m8n8.x4.trans.shared.b16 {%0,%1,%2,%3}, [%4];"
                 : "=r"(r[0]), "=r"(r[1]), "=r"(r[2]), "=r"(r[3]) : "r"(addr));
}

__device__ __forceinline__ void mma16816(float* d, const unsigned* a, const unsigned* b) {
    asm volatile("mma.sync.aligned.m16n8k16.row.col.f32.bf16.bf16.f32 "
                 "{%0,%1,%2,%3}, {%4,%5,%6,%7}, {%8,%9}, {%0,%1,%2,%3};"
                 : "+f"(d[0]), "+f"(d[1]), "+f"(d[2]), "+f"(d[3])
                 : "r"(a[0]), "r"(a[1]), "r"(a[2]), "r"(a[3]), "r"(b[0]), "r"(b[1]));
}

#define SA_STRIDE 40
#define SB_STRIDE 136

// ---------------- tensor-core GEMM (R13) ----------------
template <bool RELU, bool SOFTMAX>
__global__ __launch_bounds__(256, 2)
void mma_gemm_k(const float* __restrict__ A, const float* __restrict__ B,
                const float* __restrict__ bias, float* __restrict__ C, int M) {
    __shared__ __align__(16) unsigned short sAhi[128 * SA_STRIDE];
    __shared__ __align__(16) unsigned short sAlo[128 * SA_STRIDE];
    __shared__ __align__(16) unsigned short sBhi[32 * SB_STRIDE];
    __shared__ __align__(16) unsigned short sBlo[32 * SB_STRIDE];

    const int t = threadIdx.x;
    const int lane = t & 31;
    const int warp = t >> 5;
    const int warpM = warp >> 1;
    const int warpN = warp & 1;
    const int rowBase = blockIdx.x * 128;

    float acc[2][8][4];
#pragma unroll
    for (int i = 0; i < 2; i++)
#pragma unroll
        for (int j = 0; j < 8; j++)
#pragma unroll
            for (int k = 0; k < 4; k++) acc[i][j][k] = 0.0f;

    const unsigned sAhi_u = (unsigned)__cvta_generic_to_shared(sAhi);
    const unsigned sAlo_u = (unsigned)__cvta_generic_to_shared(sAlo);
    const unsigned sBhi_u = (unsigned)__cvta_generic_to_shared(sBhi);
    const unsigned sBlo_u = (unsigned)__cvta_generic_to_shared(sBlo);

    const int aLRow = lane & 15;
    const int aLColOff = (lane >> 4) << 3;
    const int bLK = (lane & 7) + (((lane >> 3) & 1) << 3);
    const int bLN = (lane >> 4) << 3;

    for (int kc = 0; kc < 128; kc += 32) {
#pragma unroll
        for (int i = 0; i < 4; i++) {
            int idx = t * 4 + i;
            int r = idx >> 3, c4 = idx & 7;
            float4 v = make_float4(0.f, 0.f, 0.f, 0.f);
            int gr = rowBase + r;
            if (gr < M) v = *(const float4*)(A + gr * 128 + kc + c4 * 4);
            unsigned h0, l0, h1, l1;
            split2(v.x, v.y, h0, l0);
            split2(v.z, v.w, h1, l1);
            unsigned* ph = (unsigned*)(sAhi + r * SA_STRIDE + c4 * 4);
            unsigned* pl = (unsigned*)(sAlo + r * SA_STRIDE + c4 * 4);
            ph[0] = h0; ph[1] = h1;
            pl[0] = l0; pl[1] = l1;
        }
#pragma unroll
        for (int i = 0; i < 4; i++) {
            int idx = t * 4 + i;
            int r = idx >> 5, c4 = idx & 31;
            float4 v = *(const float4*)(B + (kc + r) * 128 + c4 * 4);
            unsigned h0, l0, h1, l1;
            split2(v.x, v.y, h0, l0);
            split2(v.z, v.w, h1, l1);
            unsigned* ph = (unsigned*)(sBhi + r * SB_STRIDE + c4 * 4);
            unsigned* pl = (unsigned*)(sBlo + r * SB_STRIDE + c4 * 4);
            ph[0] = h0; ph[1] = h1;
            pl[0] = l0; pl[1] = l1;
        }
        __syncthreads();

#pragma unroll
        for (int ks = 0; ks < 2; ks++) {
            const int k0 = ks * 16;
            unsigned ahi[2][4], alo[2][4];
#pragma unroll
            for (int mt = 0; mt < 2; mt++) {
                int mrow = warpM * 32 + mt * 16 + aLRow;
                unsigned off = (unsigned)(mrow * SA_STRIDE + k0 + aLColOff) * 2u;
                ldm_x4(ahi[mt], sAhi_u + off);
                ldm_x4(alo[mt], sAlo_u + off);
            }
            unsigned bhi[8][2], blo[8][2];
#pragma unroll
            for (int nt2 = 0; nt2 < 4; nt2++) {
                if (SOFTMAX && (warpN == 1 || nt2 == 3)) continue;
                int ncol = warpN * 64 + nt2 * 16 + bLN;
                unsigned off = (unsigned)((k0 + bLK) * SB_STRIDE + ncol) * 2u;
                unsigned r4[4];
                ldm_x4t(r4, sBhi_u + off);
                bhi[nt2 * 2][0] = r4[0]; bhi[nt2 * 2][1] = r4[1];
                bhi[nt2 * 2 + 1][0] = r4[2]; bhi[nt2 * 2 + 1][1] = r4[3];
                ldm_x4t(r4, sBlo_u + off);
                blo[nt2 * 2][0] = r4[0]; blo[nt2 * 2][1] = r4[1];
                blo[nt2 * 2 + 1][0] = r4[2]; blo[nt2 * 2 + 1][1] = r4[3];
            }
#pragma unroll
            for (int mt = 0; mt < 2; mt++)
#pragma unroll
                for (int nt = 0; nt < 8; nt++) {
                    if (SOFTMAX && (warpN == 1 || nt >= 5)) continue;
                    mma16816(acc[mt][nt], ahi[mt], bhi[nt]);
                    mma16816(acc[mt][nt], ahi[mt], blo[nt]);
                    mma16816(acc[mt][nt], alo[mt], bhi[nt]);
                }
        }
        __syncthreads();
    }

    const int gid = lane >> 2, tid4 = lane & 3;

    if (SOFTMAX) {
        if (warpN == 0) {
#pragma unroll
            for (int mt = 0; mt < 2; mt++) {
#pragma unroll
                for (int half = 0; half < 2; half++) {
                    int gr = rowBase + warpM * 32 + mt * 16 + gid + half * 8;
                    float vals[10];
#pragma unroll
                    for (int nt = 0; nt < 5; nt++) {
                        int c = nt * 8 + tid4 * 2;
                        vals[nt * 2 + 0] = acc[mt][nt][half * 2 + 0] + bias[c];
                        vals[nt * 2 + 1] = acc[mt][nt][half * 2 + 1] + bias[c + 1];
                    }
                    float mx = vals[0];
#pragma unroll
                    for (int j = 1; j < 10; j++) mx = fmaxf(mx, vals[j]);
                    mx = fmaxf(mx, __shfl_xor_sync(0xffffffffu, mx, 1));
                    mx = fmaxf(mx, __shfl_xor_sync(0xffffffffu, mx, 2));
                    float s = 0.f;
#pragma unroll
                    for (int j = 0; j < 10; j++) s += expf(vals[j] - mx);
                    s += __shfl_xor_sync(0xffffffffu, s, 1);
                    s += __shfl_xor_sync(0xffffffffu, s, 2);
                    float lse = logf(s);
                    if (gr < M) {
#pragma unroll
                        for (int nt = 0; nt < 5; nt++) {
                            int c = nt * 8 + tid4 * 2;
                            float2 o;
                            o.x = vals[nt * 2 + 0] - mx - lse;
                            o.y = vals[nt * 2 + 1] - mx - lse;
                            *(float2*)(C + (size_t)gr * NC + c) = o;
                        }
                    }
                }
            }
        }
        return;
    }

#pragma unroll
    for (int mt = 0; mt < 2; mt++) {
#pragma unroll
        for (int nt = 0; nt < 8; nt++) {
            int c = warpN * 64 + nt * 8 + tid4 * 2;
            float bx = bias[c], by = bias[c + 1];
            int r0 = rowBase + warpM * 32 + mt * 16 + gid;
            if (r0 < M) {
                float2 v;
                v.x = acc[mt][nt][0] + bx;
                v.y = acc[mt][nt][1] + by;
                if (RELU) { v.x = fmaxf(v.x, 0.f); v.y = fmaxf(v.y, 0.f); }
                *(float2*)(C + r0 * 128 + c) = v;
            }
            int r1 = r0 + 8;
            if (r1 < M) {
                float2 v;
                v.x = acc[mt][nt][2] + bx;
                v.y = acc[mt][nt][3] + by;
                if (RELU) { v.x = fmaxf(v.x, 0.f); v.y = fmaxf(v.y, 0.f); }
                *(float2*)(C + r1 * 128 + c) = v;
            }
        }
    }
}

// ---------------- fused controller + aggregation (degree-sorted node order) ----------------
__global__ __launch_bounds__(256)
void aggregate_k(const float* __restrict__ Wd, const float* __restrict__ bd,
                 const float* __restrict__ Wa, const float* __restrict__ ba,
                 int first, int last) {
    int warpId = threadIdx.x >> 5;
    int lane   = threadIdx.x & 31;
    int slot   = blockIdx.x * 8 + warpId;
    if (slot >= NN) return;
    int node = g_perm[slot];          // degree-sorted: warps in a block have ~equal work

    const float4 hp = *(const float4*)(g_h + node * HH + lane * 4);
    float hv[4] = {hp.x, hp.y, hp.z, hp.w};
    float d0 = 0.f, d1 = 0.f, a0 = 0.f, a1 = 0.f, a2 = 0.f;
#pragma unroll
    for (int j = 0; j < 4; j++) {
        int k = lane * 4 + j;
        float v = hv[j];
        d0 += v * __ldg(&Wd[k * 2 + 0]);
        d1 += v * __ldg(&Wd[k * 2 + 1]);
        a0 += v * __ldg(&Wa[k * 3 + 0]);
        a1 += v * __ldg(&Wa[k * 3 + 1]);
        a2 += v * __ldg(&Wa[k * 3 + 2]);
    }
#pragma unroll
    for (int off = 16; off; off >>= 1) {
        d0 += __shfl_xor_sync(0xffffffffu, d0, off);
        d1 += __shfl_xor_sync(0xffffffffu, d1, off);
        a0 += __shfl_xor_sync(0xffffffffu, a0, off);
        a1 += __shfl_xor_sync(0xffffffffu, a1, off);
        a2 += __shfl_xor_sync(0xffffffffu, a2, off);
    }
    d0 += bd[0]; d1 += bd[1];
    a0 += ba[0]; a1 += ba[1]; a2 += ba[2];

    float md = fmaxf(d0, d1);
    float e0 = expf(d0 - md), e1 = expf(d1 - md);
    float inv2 = 1.f / (e0 + e1);
    float stop0 = e0 * inv2, stop1 = e1 * inv2;

    float ma = fmaxf(a0, fmaxf(a1, a2));
    float x0 = expf(a0 - ma), x1 = expf(a1 - ma), x2 = expf(a2 - ma);
    float inv3 = 1.f / (x0 + x1 + x2);
    float w_mean = x0 * inv3, w_max = x1 * inv3, w_self = x2 * inv3;

    float cpv  = g_cp[node];
    float csel = cpv * stop1;
    if (lane == 0 && !last) g_cp[node] = cpv * stop0;

    int start = g_offsets[node];
    int cnt   = g_counts[node];
    int end   = start + cnt;

    float4 s4  = make_float4(0.f, 0.f, 0.f, 0.f);
    float4 mx4 = make_float4(-3.4e38f, -3.4e38f, -3.4e38f, -3.4e38f);

    int e = start;
    for (; e + 4 <= end; e += 4) {
        int i0 = g_csr[e + 0], i1 = g_csr[e + 1], i2 = g_csr[e + 2], i3 = g_csr[e + 3];
        float4 v0 = *(const float4*)(g_hnew + i0 * HH + lane * 4);
        float4 v1 = *(const float4*)(g_hnew + i1 * HH + lane * 4);
        float4 v2 = *(const float4*)(g_hnew + i2 * HH + lane * 4);
        float4 v3 = *(const float4*)(g_hnew + i3 * HH + lane * 4);
        s4.x += v0.x + v1.x + v2.x + v3.x;
        s4.y += v0.y + v1.y + v2.y + v3.y;
        s4.z += v0.z + v1.z + v2.z + v3.z;
        s4.w += v0.w + v1.w + v2.w + v3.w;
        mx4.x = fmaxf(mx4.x, fmaxf(fmaxf(v0.x, v1.x), fmaxf(v2.x, v3.x)));
        mx4.y = fmaxf(mx4.y, fmaxf(fmaxf(v0.y, v1.y), fmaxf(v2.y, v3.y)));
        mx4.z = fmaxf(mx4.z, fmaxf(fmaxf(v0.z, v1.z), fmaxf(v2.z, v3.z)));
        mx4.w = fmaxf(mx4.w, fmaxf(fmaxf(v0.w, v1.w), fmaxf(v2.w, v3.w)));
    }
    for (; e < end; e++) {
        int i0 = g_csr[e];
        float4 v0 = *(const float4*)(g_hnew + i0 * HH + lane * 4);
        s4.x += v0.x; s4.y += v0.y; s4.z += v0.z; s4.w += v0.w;
        mx4.x = fmaxf(mx4.x, v0.x); mx4.y = fmaxf(mx4.y, v0.y);
        mx4.z = fmaxf(mx4.z, v0.z); mx4.w = fmaxf(mx4.w, v0.w);
    }

    float rdeg = 1.f / fmaxf((float)cnt, 1.f);
    if (cnt == 0) mx4 = make_float4(0.f, 0.f, 0.f, 0.f);

    float4 self4 = *(const float4*)(g_hnew + node * HH + lane * 4);
    float4 h4;
    h4.x = fmaxf(w_mean * (s4.x * rdeg) + w_max * mx4.x + w_self * self4.x, 0.f);
    h4.y = fmaxf(w_mean * (s4.y * rdeg) + w_max * mx4.y + w_self * self4.y, 0.f);
    h4.z = fmaxf(w_mean * (s4.z * rdeg) + w_max * mx4.z + w_self * self4.z, 0.f);
    h4.w = fmaxf(w_mean * (s4.w * rdeg) + w_max * mx4.w + w_self * self4.w, 0.f);

    if (!last) *(float4*)(g_h + node * HH + lane * 4) = h4;

    float4 sv;
    if (first) {
        sv.x = csel * h4.x; sv.y = csel * h4.y;
        sv.z = csel * h4.z; sv.w = csel * h4.w;
    } else {
        float4 pv = *(const float4*)(g_sel + node * HH + lane * 4);
        sv.x = pv.x + csel * h4.x; sv.y = pv.y + csel * h4.y;
        sv.z = pv.z + csel * h4.z; sv.w = pv.w + csel * h4.w;
    }
    *(float4*)(g_sel + node * HH + lane * 4) = sv;
}

// ---------------- launch ----------------
extern "C" void kernel_launch(void* const* d_in, const int* in_sizes, int n_in,
                              void* d_out, int out_size) {
    const float* x       = (const float*)d_in[0];
    const int*   ei      = (const int*)  d_in[1];
    const float* W_pre   = (const float*)d_in[2];
    const float* b_pre   = (const float*)d_in[3];
    const float* W_depth = (const float*)d_in[4];
    const float* b_depth = (const float*)d_in[5];
    const float* W_aggr  = (const float*)d_in[6];
    const float* b_aggr  = (const float*)d_in[7];
    const float* W_conv  = (const float*)d_in[8];
    const float* b_conv  = (const float*)d_in[9];
    const float* W_post  = (const float*)d_in[10];
    const float* b_post  = (const float*)d_in[11];
    float* out = (float*)d_out;

    const int* src = ei;
    const int* dst = ei + NE;

    float *h_ptr, *hnew_ptr, *sel_ptr, *wpad_ptr, *bpad_ptr;
    cudaGetSymbolAddress((void**)&h_ptr,    g_h);
    cudaGetSymbolAddress((void**)&hnew_ptr, g_hnew);
    cudaGetSymbolAddress((void**)&sel_ptr,  g_sel);
    cudaGetSymbolAddress((void**)&wpad_ptr, g_Wpad);
    cudaGetSymbolAddress((void**)&bpad_ptr, g_bpad);

    cudaStream_t s1;
    cudaEvent_t evF, evJ;
    cudaStreamCreateWithFlags(&s1, cudaStreamNonBlocking);
    cudaEventCreateWithFlags(&evF, cudaEventDisableTiming);
    cudaEventCreateWithFlags(&evJ, cudaEventDisableTiming);

    const int gemmGrid = (NN + 127) / 128;

    // ---- fork: CSR build + degree sort on s1 ----
    cudaEventRecord(evF, 0);
    cudaStreamWaitEvent(s1, evF, 0);

    zero_counts_k<<<NB, 1024, 0, s1>>>();
    pad_post_k<<<(HH * HH + 255) / 256, 256, 0, s1>>>(W_post, b_post);
    hist_k<<<(NE + 255) / 256, 256, 0, s1>>>(dst);
    scan1_k<<<NB, 1024, 0, s1>>>();
    scan2_k<<<1, 128, 0, s1>>>();
    scan3_k<<<NB, 1024, 0, s1>>>();
    fill_k<<<(NE + 255) / 256, 256, 0, s1>>>(src, dst);
    dscan_k<<<1, NDB, 0, s1>>>();
    dscatter_k<<<NB, 1024, 0, s1>>>();
    cudaEventRecord(evJ, s1);

    // main stream: pre GEMM + conv0 GEMM overlap the CSR build/sort
    mma_gemm_k<true, false><<<gemmGrid, 256>>>(x, W_pre, b_pre, h_ptr, NN);
    mma_gemm_k<false, false><<<gemmGrid, 256>>>(h_ptr, W_conv, b_conv, hnew_ptr, NN);

    // ---- join before first aggregate ----
    cudaStreamWaitEvent(0, evJ, 0);

    aggregate_k<<<(NN + 7) / 8, 256>>>(W_depth, b_depth, W_aggr, b_aggr, 1, 0);

    for (int i = 1; i < 4; i++) {
        mma_gemm_k<false, false><<<gemmGrid, 256>>>(h_ptr, W_conv + i * HH * HH,
                                                    b_conv + i * HH, hnew_ptr, NN);
        aggregate_k<<<(NN + 7) / 8, 256>>>(W_depth, b_depth, W_aggr, b_aggr, 0, i == 3 ? 1 : 0);
    }

    // post: logits + fused log_softmax straight to out
    mma_gemm_k<false, true><<<gemmGrid, 256>>>(sel_ptr, wpad_ptr, bpad_ptr, out, NN);
}

// round 15
// speedup vs baseline: 1.0743x; 1.0743x over previous
#include <cuda_runtime.h>
#include <math.h>

#define NN 100000
#define NE 1600000
#define HH 128
#define NC 40
#define NB 98          // ceil(NN/1024)
#define H1N 50048      // half-1 node/row count (multiple of 128)

// ---------------- scratch ----------------
__device__ float g_h[NN * HH];
__device__ float g_hnA[NN * HH];    // ping-pong transformed features
__device__ float g_hnB[NN * HH];
__device__ float g_sel[NN * HH];
__device__ float g_cp[NN];
__device__ int   g_counts[NN];
__device__ int   g_offsets[NN];
__device__ int   g_cursor[NN];
__device__ int   g_csr[NE];
__device__ int   g_bsums[128];
__device__ int   g_boffs[128];
__device__ float g_Wpad[HH * HH];
__device__ float g_bpad[HH];

// ---------------- small utility kernels ----------------
__global__ void zero_counts_k() {
    int i = blockIdx.x * blockDim.x + threadIdx.x;
    if (i < NN) g_counts[i] = 0;
}

__global__ void pad_post_k(const float* __restrict__ Wp, const float* __restrict__ bp) {
    int i = blockIdx.x * blockDim.x + threadIdx.x;
    if (i < HH * HH) {
        int k = i / HH, c = i % HH;
        g_Wpad[i] = (c < NC) ? Wp[k * NC + c] : 0.0f;
    }
    if (i < HH) g_bpad[i] = (i < NC) ? bp[i] : 0.0f;
}

__global__ void hist_k(const int* __restrict__ dst) {
    int e = blockIdx.x * blockDim.x + threadIdx.x;
    if (e < NE) atomicAdd(&g_counts[dst[e]], 1);
}

__global__ void scan1_k() {
    __shared__ int sh[1024];
    int t = threadIdx.x;
    int i = blockIdx.x * 1024 + t;
    int v = (i < NN) ? g_counts[i] : 0;
    sh[t] = v;
    __syncthreads();
#pragma unroll
    for (int off = 1; off < 1024; off <<= 1) {
        int x = 0;
        if (t >= off) x = sh[t - off];
        __syncthreads();
        if (t >= off) sh[t] += x;
        __syncthreads();
    }
    int incl = sh[t];
    if (i < NN) g_offsets[i] = incl - v;
    if (t == 1023) g_bsums[blockIdx.x] = incl;
}

__global__ void scan2_k() {
    __shared__ int sh[128];
    int t = threadIdx.x;
    int v = (t < NB) ? g_bsums[t] : 0;
    sh[t] = v;
    __syncthreads();
#pragma unroll
    for (int off = 1; off < 128; off <<= 1) {
        int x = 0;
        if (t >= off) x = sh[t - off];
        __syncthreads();
        if (t >= off) sh[t] += x;
        __syncthreads();
    }
    g_boffs[t] = sh[t] - v;
}

__global__ void scan3_k() {
    int i = blockIdx.x * 1024 + threadIdx.x;
    if (i < NN) {
        int off = g_offsets[i] + g_boffs[blockIdx.x];
        g_offsets[i] = off;
        g_cursor[i]  = off;
        g_cp[i]      = 1.0f;
    }
}

__global__ void fill_k(const int* __restrict__ src, const int* __restrict__ dst) {
    int e = blockIdx.x * blockDim.x + threadIdx.x;
    if (e < NE) {
        int d = dst[e];
        int p = atomicAdd(&g_cursor[d], 1);
        g_csr[p] = src[e];
    }
}

// ---------------- bf16 split helpers ----------------
__device__ __forceinline__ unsigned bf16rn(float f) {
    unsigned b = __float_as_uint(f);
    return (b + 0x7fffu + ((b >> 16) & 1u)) >> 16;   // RNE
}

__device__ __forceinline__ void split2(float x, float y, unsigned& hi, unsigned& lo) {
    unsigned hx = bf16rn(x), hy = bf16rn(y);
    float rx = x - __uint_as_float(hx << 16);
    float ry = y - __uint_as_float(hy << 16);
    hi = hx | (hy << 16);
    lo = bf16rn(rx) | (bf16rn(ry) << 16);
}

// ---------------- MMA helpers ----------------
__device__ __forceinline__ void ldm_x4(unsigned* r, unsigned addr) {
    asm volatile("ldmatrix.sync.aligned.m8n8.x4.shared.b16 {%0,%1,%2,%3}, [%4];"
                 : "=r"(r[0]), "=r"(r[1]), "=r"(r[2]), "=r"(r[3]) : "r"(addr));
}

__device__ __forceinline__ void ldm_x4t(unsigned* r, unsigned addr) {
    asm volatile("ldmatrix.sync.aligned.m8n8.x4.trans.shared.b16 {%0,%1,%2,%3}, [%4];"
                 : "=r"(r[0]), "=r"(r[1]), "=r"(r[2]), "=r"(r[3]) : "r"(addr));
}

__device__ __forceinline__ void mma16816(float* d, const unsigned* a, const unsigned* b) {
    asm volatile("mma.sync.aligned.m16n8k16.row.col.f32.bf16.bf16.f32 "
                 "{%0,%1,%2,%3}, {%4,%5,%6,%7}, {%8,%9}, {%0,%1,%2,%3};"
                 : "+f"(d[0]), "+f"(d[1]), "+f"(d[2]), "+f"(d[3])
                 : "r"(a[0]), "r"(a[1]), "r"(a[2]), "r"(a[3]), "r"(b[0]), "r"(b[1]));
}

#define SA_STRIDE 40
#define SB_STRIDE 136

// ---------------- tensor-core GEMM (R13 body + row offset) ----------------
template <bool RELU, bool SOFTMAX>
__global__ __launch_bounds__(256, 2)
void mma_gemm_k(const float* __restrict__ A, const float* __restrict__ B,
                const float* __restrict__ bias, float* __restrict__ C,
                int M, int rowOff) {
    __shared__ __align__(16) unsigned short sAhi[128 * SA_STRIDE];
    __shared__ __align__(16) unsigned short sAlo[128 * SA_STRIDE];
    __shared__ __align__(16) unsigned short sBhi[32 * SB_STRIDE];
    __shared__ __align__(16) unsigned short sBlo[32 * SB_STRIDE];

    const int t = threadIdx.x;
    const int lane = t & 31;
    const int warp = t >> 5;
    const int warpM = warp >> 1;
    const int warpN = warp & 1;
    const int rowBase = rowOff + blockIdx.x * 128;

    float acc[2][8][4];
#pragma unroll
    for (int i = 0; i < 2; i++)
#pragma unroll
        for (int j = 0; j < 8; j++)
#pragma unroll
            for (int k = 0; k < 4; k++) acc[i][j][k] = 0.0f;

    const unsigned sAhi_u = (unsigned)__cvta_generic_to_shared(sAhi);
    const unsigned sAlo_u = (unsigned)__cvta_generic_to_shared(sAlo);
    const unsigned sBhi_u = (unsigned)__cvta_generic_to_shared(sBhi);
    const unsigned sBlo_u = (unsigned)__cvta_generic_to_shared(sBlo);

    const int aLRow = lane & 15;
    const int aLColOff = (lane >> 4) << 3;
    const int bLK = (lane & 7) + (((lane >> 3) & 1) << 3);
    const int bLN = (lane >> 4) << 3;

    for (int kc = 0; kc < 128; kc += 32) {
#pragma unroll
        for (int i = 0; i < 4; i++) {
            int idx = t * 4 + i;
            int r = idx >> 3, c4 = idx & 7;
            float4 v = make_float4(0.f, 0.f, 0.f, 0.f);
            int gr = rowBase + r;
            if (gr < M) v = *(const float4*)(A + (size_t)gr * 128 + kc + c4 * 4);
            unsigned h0, l0, h1, l1;
            split2(v.x, v.y, h0, l0);
            split2(v.z, v.w, h1, l1);
            unsigned* ph = (unsigned*)(sAhi + r * SA_STRIDE + c4 * 4);
            unsigned* pl = (unsigned*)(sAlo + r * SA_STRIDE + c4 * 4);
            ph[0] = h0; ph[1] = h1;
            pl[0] = l0; pl[1] = l1;
        }
#pragma unroll
        for (int i = 0; i < 4; i++) {
            int idx = t * 4 + i;
            int r = idx >> 5, c4 = idx & 31;
            float4 v = *(const float4*)(B + (kc + r) * 128 + c4 * 4);
            unsigned h0, l0, h1, l1;
            split2(v.x, v.y, h0, l0);
            split2(v.z, v.w, h1, l1);
            unsigned* ph = (unsigned*)(sBhi + r * SB_STRIDE + c4 * 4);
            unsigned* pl = (unsigned*)(sBlo + r * SB_STRIDE + c4 * 4);
            ph[0] = h0; ph[1] = h1;
            pl[0] = l0; pl[1] = l1;
        }
        __syncthreads();

#pragma unroll
        for (int ks = 0; ks < 2; ks++) {
            const int k0 = ks * 16;
            unsigned ahi[2][4], alo[2][4];
#pragma unroll
            for (int mt = 0; mt < 2; mt++) {
                int mrow = warpM * 32 + mt * 16 + aLRow;
                unsigned off = (unsigned)(mrow * SA_STRIDE + k0 + aLColOff) * 2u;
                ldm_x4(ahi[mt], sAhi_u + off);
                ldm_x4(alo[mt], sAlo_u + off);
            }
            unsigned bhi[8][2], blo[8][2];
#pragma unroll
            for (int nt2 = 0; nt2 < 4; nt2++) {
                if (SOFTMAX && (warpN == 1 || nt2 == 3)) continue;
                int ncol = warpN * 64 + nt2 * 16 + bLN;
                unsigned off = (unsigned)((k0 + bLK) * SB_STRIDE + ncol) * 2u;
                unsigned r4[4];
                ldm_x4t(r4, sBhi_u + off);
                bhi[nt2 * 2][0] = r4[0]; bhi[nt2 * 2][1] = r4[1];
                bhi[nt2 * 2 + 1][0] = r4[2]; bhi[nt2 * 2 + 1][1] = r4[3];
                ldm_x4t(r4, sBlo_u + off);
                blo[nt2 * 2][0] = r4[0]; blo[nt2 * 2][1] = r4[1];
                blo[nt2 * 2 + 1][0] = r4[2]; blo[nt2 * 2 + 1][1] = r4[3];
            }
#pragma unroll
            for (int mt = 0; mt < 2; mt++)
#pragma unroll
                for (int nt = 0; nt < 8; nt++) {
                    if (SOFTMAX && (warpN == 1 || nt >= 5)) continue;
                    mma16816(acc[mt][nt], ahi[mt], bhi[nt]);
                    mma16816(acc[mt][nt], ahi[mt], blo[nt]);
                    mma16816(acc[mt][nt], alo[mt], bhi[nt]);
                }
        }
        __syncthreads();
    }

    const int gid = lane >> 2, tid4 = lane & 3;

    if (SOFTMAX) {
        if (warpN == 0) {
#pragma unroll
            for (int mt = 0; mt < 2; mt++) {
#pragma unroll
                for (int half = 0; half < 2; half++) {
                    int gr = rowBase + warpM * 32 + mt * 16 + gid + half * 8;
                    float vals[10];
#pragma unroll
                    for (int nt = 0; nt < 5; nt++) {
                        int c = nt * 8 + tid4 * 2;
                        vals[nt * 2 + 0] = acc[mt][nt][half * 2 + 0] + bias[c];
                        vals[nt * 2 + 1] = acc[mt][nt][half * 2 + 1] + bias[c + 1];
                    }
                    float mx = vals[0];
#pragma unroll
                    for (int j = 1; j < 10; j++) mx = fmaxf(mx, vals[j]);
                    mx = fmaxf(mx, __shfl_xor_sync(0xffffffffu, mx, 1));
                    mx = fmaxf(mx, __shfl_xor_sync(0xffffffffu, mx, 2));
                    float s = 0.f;
#pragma unroll
                    for (int j = 0; j < 10; j++) s += expf(vals[j] - mx);
                    s += __shfl_xor_sync(0xffffffffu, s, 1);
                    s += __shfl_xor_sync(0xffffffffu, s, 2);
                    float lse = logf(s);
                    if (gr < M) {
#pragma unroll
                        for (int nt = 0; nt < 5; nt++) {
                            int c = nt * 8 + tid4 * 2;
                            float2 o;
                            o.x = vals[nt * 2 + 0] - mx - lse;
                            o.y = vals[nt * 2 + 1] - mx - lse;
                            *(float2*)(C + (size_t)gr * NC + c) = o;
                        }
                    }
                }
            }
        }
        return;
    }

#pragma unroll
    for (int mt = 0; mt < 2; mt++) {
#pragma unroll
        for (int nt = 0; nt < 8; nt++) {
            int c = warpN * 64 + nt * 8 + tid4 * 2;
            float bx = bias[c], by = bias[c + 1];
            int r0 = rowBase + warpM * 32 + mt * 16 + gid;
            if (r0 < M) {
                float2 v;
                v.x = acc[mt][nt][0] + bx;
                v.y = acc[mt][nt][1] + by;
                if (RELU) { v.x = fmaxf(v.x, 0.f); v.y = fmaxf(v.y, 0.f); }
                *(float2*)(C + (size_t)r0 * 128 + c) = v;
            }
            int r1 = r0 + 8;
            if (r1 < M) {
                float2 v;
                v.x = acc[mt][nt][2] + bx;
                v.y = acc[mt][nt][3] + by;
                if (RELU) { v.x = fmaxf(v.x, 0.f); v.y = fmaxf(v.y, 0.f); }
                *(float2*)(C + (size_t)r1 * 128 + c) = v;
            }
        }
    }
}

// ---------------- fused controller + aggregation (R13 body + node range) ----------------
__global__ __launch_bounds__(256)
void aggregate_k(const float* __restrict__ hnew,
                 const float* __restrict__ Wd, const float* __restrict__ bd,
                 const float* __restrict__ Wa, const float* __restrict__ ba,
                 int first, int last, int nodeOff, int nodeEnd) {
    int warpId = threadIdx.x >> 5;
    int lane   = threadIdx.x & 31;
    int node   = nodeOff + blockIdx.x * 8 + warpId;
    if (node >= nodeEnd) return;

    const float4 hp = *(const float4*)(g_h + (size_t)node * HH + lane * 4);
    float hv[4] = {hp.x, hp.y, hp.z, hp.w};
    float d0 = 0.f, d1 = 0.f, a0 = 0.f, a1 = 0.f, a2 = 0.f;
#pragma unroll
    for (int j = 0; j < 4; j++) {
        int k = lane * 4 + j;
        float v = hv[j];
        d0 += v * __ldg(&Wd[k * 2 + 0]);
        d1 += v * __ldg(&Wd[k * 2 + 1]);
        a0 += v * __ldg(&Wa[k * 3 + 0]);
        a1 += v * __ldg(&Wa[k * 3 + 1]);
        a2 += v * __ldg(&Wa[k * 3 + 2]);
    }
#pragma unroll
    for (int off = 16; off; off >>= 1) {
        d0 += __shfl_xor_sync(0xffffffffu, d0, off);
        d1 += __shfl_xor_sync(0xffffffffu, d1, off);
        a0 += __shfl_xor_sync(0xffffffffu, a0, off);
        a1 += __shfl_xor_sync(0xffffffffu, a1, off);
        a2 += __shfl_xor_sync(0xffffffffu, a2, off);
    }
    d0 += bd[0]; d1 += bd[1];
    a0 += ba[0]; a1 += ba[1]; a2 += ba[2];

    float md = fmaxf(d0, d1);
    float e0 = expf(d0 - md), e1 = expf(d1 - md);
    float inv2 = 1.f / (e0 + e1);
    float stop0 = e0 * inv2, stop1 = e1 * inv2;

    float ma = fmaxf(a0, fmaxf(a1, a2));
    float x0 = expf(a0 - ma), x1 = expf(a1 - ma), x2 = expf(a2 - ma);
    float inv3 = 1.f / (x0 + x1 + x2);
    float w_mean = x0 * inv3, w_max = x1 * inv3, w_self = x2 * inv3;

    float cpv  = g_cp[node];
    float csel = cpv * stop1;
    if (lane == 0 && !last) g_cp[node] = cpv * stop0;

    int start = g_offsets[node];
    int cnt   = g_counts[node];
    int end   = start + cnt;

    float4 s4  = make_float4(0.f, 0.f, 0.f, 0.f);
    float4 mx4 = make_float4(-3.4e38f, -3.4e38f, -3.4e38f, -3.4e38f);

    int e = start;
    for (; e + 4 <= end; e += 4) {
        int i0 = g_csr[e + 0], i1 = g_csr[e + 1], i2 = g_csr[e + 2], i3 = g_csr[e + 3];
        float4 v0 = *(const float4*)(hnew + (size_t)i0 * HH + lane * 4);
        float4 v1 = *(const float4*)(hnew + (size_t)i1 * HH + lane * 4);
        float4 v2 = *(const float4*)(hnew + (size_t)i2 * HH + lane * 4);
        float4 v3 = *(const float4*)(hnew + (size_t)i3 * HH + lane * 4);
        s4.x += v0.x + v1.x + v2.x + v3.x;
        s4.y += v0.y + v1.y + v2.y + v3.y;
        s4.z += v0.z + v1.z + v2.z + v3.z;
        s4.w += v0.w + v1.w + v2.w + v3.w;
        mx4.x = fmaxf(mx4.x, fmaxf(fmaxf(v0.x, v1.x), fmaxf(v2.x, v3.x)));
        mx4.y = fmaxf(mx4.y, fmaxf(fmaxf(v0.y, v1.y), fmaxf(v2.y, v3.y)));
        mx4.z = fmaxf(mx4.z, fmaxf(fmaxf(v0.z, v1.z), fmaxf(v2.z, v3.z)));
        mx4.w = fmaxf(mx4.w, fmaxf(fmaxf(v0.w, v1.w), fmaxf(v2.w, v3.w)));
    }
    for (; e < end; e++) {
        int i0 = g_csr[e];
        float4 v0 = *(const float4*)(hnew + (size_t)i0 * HH + lane * 4);
        s4.x += v0.x; s4.y += v0.y; s4.z += v0.z; s4.w += v0.w;
        mx4.x = fmaxf(mx4.x, v0.x); mx4.y = fmaxf(mx4.y, v0.y);
        mx4.z = fmaxf(mx4.z, v0.z); mx4.w = fmaxf(mx4.w, v0.w);
    }

    float rdeg = 1.f / fmaxf((float)cnt, 1.f);
    if (cnt == 0) mx4 = make_float4(0.f, 0.f, 0.f, 0.f);

    float4 self4 = *(const float4*)(hnew + (size_t)node * HH + lane * 4);
    float4 h4;
    h4.x = fmaxf(w_mean * (s4.x * rdeg) + w_max * mx4.x + w_self * self4.x, 0.f);
    h4.y = fmaxf(w_mean * (s4.y * rdeg) + w_max * mx4.y + w_self * self4.y, 0.f);
    h4.z = fmaxf(w_mean * (s4.z * rdeg) + w_max * mx4.z + w_self * self4.z, 0.f);
    h4.w = fmaxf(w_mean * (s4.w * rdeg) + w_max * mx4.w + w_self * self4.w, 0.f);

    if (!last) *(float4*)(g_h + (size_t)node * HH + lane * 4) = h4;

    float4 sv;
    if (first) {
        sv.x = csel * h4.x; sv.y = csel * h4.y;
        sv.z = csel * h4.z; sv.w = csel * h4.w;
    } else {
        float4 pv = *(const float4*)(g_sel + (size_t)node * HH + lane * 4);
        sv.x = pv.x + csel * h4.x; sv.y = pv.y + csel * h4.y;
        sv.z = pv.z + csel * h4.z; sv.w = pv.w + csel * h4.w;
    }
    *(float4*)(g_sel + (size_t)node * HH + lane * 4) = sv;
}

// ---------------- launch: two-stream half-pipelined layer chain ----------------
extern "C" void kernel_launch(void* const* d_in, const int* in_sizes, int n_in,
                              void* d_out, int out_size) {
    const float* x       = (const float*)d_in[0];
    const int*   ei      = (const int*)  d_in[1];
    const float* W_pre   = (const float*)d_in[2];
    const float* b_pre   = (const float*)d_in[3];
    const float* W_depth = (const float*)d_in[4];
    const float* b_depth = (const float*)d_in[5];
    const float* W_aggr  = (const float*)d_in[6];
    const float* b_aggr  = (const float*)d_in[7];
    const float* W_conv  = (const float*)d_in[8];
    const float* b_conv  = (const float*)d_in[9];
    const float* W_post  = (const float*)d_in[10];
    const float* b_post  = (const float*)d_in[11];
    float* out = (float*)d_out;

    const int* src = ei;
    const int* dst = ei + NE;

    float *h_ptr, *hnA_ptr, *hnB_ptr, *sel_ptr, *wpad_ptr, *bpad_ptr;
    cudaGetSymbolAddress((void**)&h_ptr,   g_h);
    cudaGetSymbolAddress((void**)&hnA_ptr, g_hnA);
    cudaGetSymbolAddress((void**)&hnB_ptr, g_hnB);
    cudaGetSymbolAddress((void**)&sel_ptr, g_sel);
    cudaGetSymbolAddress((void**)&wpad_ptr, g_Wpad);
    cudaGetSymbolAddress((void**)&bpad_ptr, g_bpad);

    cudaStream_t s1;
    cudaStreamCreateWithFlags(&s1, cudaStreamNonBlocking);
    cudaEvent_t evF, evJ, evG0, evG1[4], evG2[4], evA2last;
    cudaEventCreateWithFlags(&evF, cudaEventDisableTiming);
    cudaEventCreateWithFlags(&evJ, cudaEventDisableTiming);
    cudaEventCreateWithFlags(&evG0, cudaEventDisableTiming);
    cudaEventCreateWithFlags(&evA2last, cudaEventDisableTiming);
    for (int i = 0; i < 4; i++) {
        cudaEventCreateWithFlags(&evG1[i], cudaEventDisableTiming);
        cudaEventCreateWithFlags(&evG2[i], cudaEventDisableTiming);
    }

    const int gemmGridFull = (NN + 127) / 128;       // 782
    const int gG1 = H1N / 128;                       // 391
    const int gG2 = (NN - H1N + 127) / 128;          // 391
    const int gA1 = H1N / 8;                         // 6256
    const int gA2 = (NN - H1N + 7) / 8;              // 6244

    float* buf[2] = { hnA_ptr, hnB_ptr };

    // ---- fork: CSR build on s1 ----
    cudaEventRecord(evF, 0);
    cudaStreamWaitEvent(s1, evF, 0);
    zero_counts_k<<<NB, 1024, 0, s1>>>();
    pad_post_k<<<(HH * HH + 255) / 256, 256, 0, s1>>>(W_post, b_post);
    hist_k<<<(NE + 255) / 256, 256, 0, s1>>>(dst);
    scan1_k<<<NB, 1024, 0, s1>>>();
    scan2_k<<<1, 128, 0, s1>>>();
    scan3_k<<<NB, 1024, 0, s1>>>();
    fill_k<<<(NE + 255) / 256, 256, 0, s1>>>(src, dst);
    cudaEventRecord(evJ, s1);

    // ---- main stream: pre GEMM + conv0 GEMM (full), overlapping CSR build ----
    mma_gemm_k<true, false><<<gemmGridFull, 256>>>(x, W_pre, b_pre, h_ptr, NN, 0);
    mma_gemm_k<false, false><<<gemmGridFull, 256>>>(h_ptr, W_conv, b_conv, buf[0], NN, 0);
    cudaEventRecord(evG0, 0);

    // join CSR on s0; s1 waits conv0 GEMM
    cudaStreamWaitEvent(0, evJ, 0);
    cudaStreamWaitEvent(s1, evG0, 0);

    for (int i = 0; i < 4; i++) {
        float* rd = buf[i & 1];
        float* wr = buf[(i + 1) & 1];
        int first = (i == 0) ? 1 : 0;
        int last  = (i == 3) ? 1 : 0;

        // aggregate halves (both streams; cross-deps already satisfied)
        aggregate_k<<<gA1, 256>>>(rd, W_depth, b_depth, W_aggr, b_aggr,
                                  first, last, 0, H1N);
        aggregate_k<<<gA2, 256, 0, s1>>>(rd, W_depth, b_depth, W_aggr, b_aggr,
                                         first, last, H1N, NN);
        if (i < 3) {
            // next conv GEMM halves: each depends only on its own stream's aggregate half
            mma_gemm_k<false, false><<<gG1, 256>>>(h_ptr, W_conv + (i + 1) * HH * HH,
                                                   b_conv + (i + 1) * HH, wr, NN, 0);
            cudaEventRecord(evG1[i], 0);
            mma_gemm_k<false, false><<<gG2, 256, 0, s1>>>(h_ptr, W_conv + (i + 1) * HH * HH,
                                                          b_conv + (i + 1) * HH, wr, NN, H1N);
            cudaEventRecord(evG2[i], s1);
            // next aggregates need BOTH GEMM halves
            cudaStreamWaitEvent(0, evG2[i], 0);
            cudaStreamWaitEvent(s1, evG1[i], 0);
        } else {
            cudaEventRecord(evA2last, s1);
        }
    }

    // post GEMM needs full g_sel
    cudaStreamWaitEvent(0, evA2last, 0);
    mma_gemm_k<false, true><<<gemmGridFull, 256>>>(sel_ptr, wpad_ptr, bpad_ptr, out, NN, 0);
}